// round 2
// baseline (speedup 1.0000x reference)
#include <cuda_runtime.h>
#include <cstdint>

#define HIDDEN 1024
#define EPSF 1e-6f

typedef unsigned long long ull;

// Scratch (allocation-free rule: __device__ globals)
__device__ float g_Q[24 * 128 * 128];       // 1.5 MB: orthogonal rotation blocks
__device__ float g_Wrot[3072 * 1024];       // 12 MB: rotated weight (filt)

// ---------------------------------------------------------------------------
// Stage 1: Cayley. Q = (2+eps) * inv(I + S + eps I) - I,  S = 0.5(A - A^T).
// One CTA per 128x128 block (24 total). In-place Gauss-Jordan, no pivoting
// (I+S has SPD symmetric part -> stable). 256 threads: thread = (row, half).
// ---------------------------------------------------------------------------
__global__ void cayley_kernel(const float* __restrict__ qR,
                              const float* __restrict__ kR,
                              const float* __restrict__ vR) {
    extern __shared__ float a[];           // 128 x 129 (padded, conflict-free col writes)
    const int P = 129;
    const int idx  = blockIdx.x;           // 0..23
    const int proj = idx >> 3;
    const int n    = idx & 7;
    const float* src = (proj == 0 ? qR : (proj == 1 ? kR : vR)) + n * 128 * 128;

    const int tid = threadIdx.x;
    const int r   = tid & 127;
    const int h   = tid >> 7;              // column half 0/1
    const int c0  = h * 64;

    // Build M = I + S + eps I
    #pragma unroll 4
    for (int j = 0; j < 64; ++j) {
        int c = c0 + j;
        float v = 0.5f * (src[r * 128 + c] - src[c * 128 + r]);
        if (c == r) v += 1.0f + EPSF;
        a[r * P + c] = v;
    }
    __syncthreads();

    for (int k = 0; k < 128; ++k) {
        float piv    = a[k * P + k];
        float pivinv = 1.0f / piv;
        float f      = a[r * P + k];
        __syncthreads();                   // reads done before row k is scaled
        if (r == k) {
            #pragma unroll 4
            for (int j = 0; j < 64; ++j) a[k * P + c0 + j] *= pivinv;
            if (k >= c0 && k < c0 + 64) a[k * P + k] = pivinv;
        }
        __syncthreads();                   // row k scaled
        if (r != k) {
            #pragma unroll 8
            for (int j = 0; j < 64; ++j) {
                int c = c0 + j;
                a[r * P + c] = fmaf(-f, a[k * P + c], a[r * P + c]);
            }
            if (k >= c0 && k < c0 + 64) a[r * P + k] = -f * pivinv;
        }
        __syncthreads();                   // elimination done before next reads
    }

    // Q = (2+eps) * Minv - I
    float* dst = g_Q + idx * 16384;
    const float s = 2.0f + EPSF;
    #pragma unroll 4
    for (int j = 0; j < 64; ++j) {
        int c = c0 + j;
        float v = s * a[r * P + c];
        if (c == r) v -= 1.0f;
        dst[r * 128 + c] = v;
    }
}

// ---------------------------------------------------------------------------
// Stage 2: Wrot[o][n*128+c] = sum_b W[o][n*128+b] * Q[idx][b][c]
// grid.x = 24 (proj,n), grid.y = 8 (o-tile of 128 rows). 256 threads:
// thread = (c, o-half). W reads are warp-uniform (L1 broadcast).
// ---------------------------------------------------------------------------
__global__ void rotate_kernel(const float* __restrict__ W) {
    extern __shared__ float Qs[];          // 128*128 f32 = 64 KB
    const int idx   = blockIdx.x;
    const int proj  = idx >> 3;
    const int n     = idx & 7;
    const int obase = proj * 1024 + blockIdx.y * 128;
    const int cbase = n * 128;
    const int tid   = threadIdx.x;

    for (int i = tid; i < 128 * 128; i += 256) Qs[i] = g_Q[idx * 16384 + i];
    __syncthreads();

    const int c    = tid & 127;
    const int half = tid >> 7;
    const float* Wp = W + (size_t)obase * 1024 + cbase;
    float*       Op = g_Wrot + (size_t)obase * 1024 + cbase;

    for (int oc = half * 64; oc < half * 64 + 64; oc += 4) {
        float a0 = 0.f, a1 = 0.f, a2 = 0.f, a3 = 0.f;
        #pragma unroll 4
        for (int b = 0; b < 128; ++b) {
            float q = Qs[b * 128 + c];
            a0 = fmaf(Wp[(size_t)(oc + 0) * 1024 + b], q, a0);
            a1 = fmaf(Wp[(size_t)(oc + 1) * 1024 + b], q, a1);
            a2 = fmaf(Wp[(size_t)(oc + 2) * 1024 + b], q, a2);
            a3 = fmaf(Wp[(size_t)(oc + 3) * 1024 + b], q, a3);
        }
        Op[(size_t)(oc + 0) * 1024 + c] = a0;
        Op[(size_t)(oc + 1) * 1024 + c] = a1;
        Op[(size_t)(oc + 2) * 1024 + c] = a2;
        Op[(size_t)(oc + 3) * 1024 + c] = a3;
    }
}

// ---------------------------------------------------------------------------
// Stage 3: out[m][o] = dot(x[m,:], Wrot[o,:]) + bias[o]
// M=32768, N=3072, K=1024. Tile 128x128x16, 256 threads, 8x8 microtile,
// packed fp32x2 FMA (FFMA2) -> 2x the scalar FFMA rate on sm_103a.
// ---------------------------------------------------------------------------
#define BM 128
#define BN 128
#define BK 16
#define PA 132

__device__ __forceinline__ ull pack_dup(float x) {
    ull d;
    unsigned u = __float_as_uint(x);
    asm("mov.b64 %0, {%1, %1};" : "=l"(d) : "r"(u));
    return d;
}
__device__ __forceinline__ void unpack2(ull d, float& lo, float& hi) {
    unsigned ulo, uhi;
    asm("mov.b64 {%0, %1}, %2;" : "=r"(ulo), "=r"(uhi) : "l"(d));
    lo = __uint_as_float(ulo);
    hi = __uint_as_float(uhi);
}

__global__ __launch_bounds__(256, 2)
void gemm_kernel(const float* __restrict__ A,      // x  [32768,1024]
                 const float* __restrict__ bias,   // [3072]
                 float* __restrict__ C) {          // [32768,3072]
    __shared__ float As[BK * PA];
    __shared__ float Bs[BK * PA];
    const float* B = g_Wrot;                       // [3072,1024]

    const int tid = threadIdx.x;
    const int m0  = blockIdx.y * BM;
    const int n0  = blockIdx.x * BN;
    const int tr8 = (tid >> 4) * 8;
    const int tc8 = (tid & 15) * 8;

    ull acc[8][4];
    #pragma unroll
    for (int i = 0; i < 8; ++i)
        #pragma unroll
        for (int j = 0; j < 4; ++j) acc[i][j] = 0ull;

    const int lrow = tid >> 2;                     // 0..63
    const int lkq  = (tid & 3) * 4;                // 0,4,8,12
    const float* Ag = A + (size_t)(m0 + lrow) * 1024 + lkq;
    const float* Bg = B + (size_t)(n0 + lrow) * 1024 + lkq;

    for (int kt = 0; kt < 1024; kt += BK) {
        #pragma unroll
        for (int j = 0; j < 2; ++j) {
            const int row = lrow + j * 64;
            float4 av = *(const float4*)(Ag + (size_t)j * 64 * 1024 + kt);
            float4 bv = *(const float4*)(Bg + (size_t)j * 64 * 1024 + kt);
            As[(lkq + 0) * PA + row] = av.x;
            As[(lkq + 1) * PA + row] = av.y;
            As[(lkq + 2) * PA + row] = av.z;
            As[(lkq + 3) * PA + row] = av.w;
            Bs[(lkq + 0) * PA + row] = bv.x;
            Bs[(lkq + 1) * PA + row] = bv.y;
            Bs[(lkq + 2) * PA + row] = bv.z;
            Bs[(lkq + 3) * PA + row] = bv.w;
        }
        __syncthreads();

        #pragma unroll
        for (int kk = 0; kk < BK; ++kk) {
            const float* ap = &As[kk * PA + tr8];
            const float* bp = &Bs[kk * PA + tc8];
            float4 a0 = *(const float4*)(ap);
            float4 a1 = *(const float4*)(ap + 4);
            ull b0 = *(const ull*)(bp + 0);
            ull b1 = *(const ull*)(bp + 2);
            ull b2 = *(const ull*)(bp + 4);
            ull b3 = *(const ull*)(bp + 6);
            float av[8] = {a0.x, a0.y, a0.z, a0.w, a1.x, a1.y, a1.z, a1.w};
            #pragma unroll
            for (int i = 0; i < 8; ++i) {
                ull ad = pack_dup(av[i]);
                asm("fma.rn.f32x2 %0, %1, %2, %0;" : "+l"(acc[i][0]) : "l"(ad), "l"(b0));
                asm("fma.rn.f32x2 %0, %1, %2, %0;" : "+l"(acc[i][1]) : "l"(ad), "l"(b1));
                asm("fma.rn.f32x2 %0, %1, %2, %0;" : "+l"(acc[i][2]) : "l"(ad), "l"(b2));
                asm("fma.rn.f32x2 %0, %1, %2, %0;" : "+l"(acc[i][3]) : "l"(ad), "l"(b3));
            }
        }
        __syncthreads();
    }

    // Epilogue: unpack, add bias, vectorized stores
    float bj[8];
    #pragma unroll
    for (int j = 0; j < 8; ++j) bj[j] = bias[n0 + tc8 + j];

    #pragma unroll
    for (int i = 0; i < 8; ++i) {
        float v[8];
        #pragma unroll
        for (int j = 0; j < 4; ++j) unpack2(acc[i][j], v[2 * j], v[2 * j + 1]);
        float4 o0 = make_float4(v[0] + bj[0], v[1] + bj[1], v[2] + bj[2], v[3] + bj[3]);
        float4 o1 = make_float4(v[4] + bj[4], v[5] + bj[5], v[6] + bj[6], v[7] + bj[7]);
        float* cp = C + (size_t)(m0 + tr8 + i) * 3072 + n0 + tc8;
        *(float4*)(cp)     = o0;
        *(float4*)(cp + 4) = o1;
    }
}

// ---------------------------------------------------------------------------
extern "C" void kernel_launch(void* const* d_in, const int* in_sizes, int n_in,
                              void* d_out, int out_size) {
    const float* W    = (const float*)d_in[0];   // attn_weight [3072,1024]
    const float* bias = (const float*)d_in[1];   // [3072]
    const float* x    = (const float*)d_in[2];   // [8,4096,1024]
    const float* qR   = (const float*)d_in[3];
    const float* kR   = (const float*)d_in[4];
    const float* vR   = (const float*)d_in[5];
    float* out = (float*)d_out;                  // [8,4096,3072]

    cudaFuncSetAttribute(cayley_kernel,
                         cudaFuncAttributeMaxDynamicSharedMemorySize, 128 * 129 * 4);
    cudaFuncSetAttribute(rotate_kernel,
                         cudaFuncAttributeMaxDynamicSharedMemorySize, 128 * 128 * 4);

    cayley_kernel<<<24, 256, 128 * 129 * 4>>>(qR, kR, vR);
    rotate_kernel<<<dim3(24, 8), 256, 128 * 128 * 4>>>(W);
    gemm_kernel<<<dim3(3072 / BN, 32768 / BM), 256>>>(x, bias, out);
}